// round 1
// baseline (speedup 1.0000x reference)
#include <cuda_runtime.h>
#include <cuda_bf16.h>

// Problem dims (fixed by reference setup_inputs)
#define BATCH 8
#define CCH   512      // channels
#define NPIX  1024     // 32*32
#define QKVC  1536     // 3*8*64
#define HEADS 8
#define DH    64
#define BHTOT 64       // BATCH*HEADS
#define EPSLN 1e-5f
#define SCALE 0.125f   // 64^-0.5

// Scratch (device globals: allocation-free contract)
__device__ float g_xn [(size_t)BATCH * CCH  * NPIX];   // 16.8 MB  normalized input [b][c][n]
__device__ float g_qkv[(size_t)BATCH * QKVC * NPIX];   // 50 MB    [b][o][n]; q:0-511 k:512-1023 v:1024-1535
__device__ float g_sim[(size_t)BHTOT * NPIX * NPIX];   // 256 MB   [bh][i][j]
__device__ float g_att[(size_t)BATCH * CCH  * NPIX];   // 16.8 MB  attention out [b][h*64+c][n]

// ---------------------------------------------------------------------------
// 1) Channel LayerNorm: per pixel (b,n) over 512 channels, biased variance.
//    Block (32 pixels x 8 c-groups); coalesced along n.
// ---------------------------------------------------------------------------
__global__ void ln_kernel(const float* __restrict__ x,
                          const float* __restrict__ gamma,
                          float* __restrict__ xn) {
    int b  = blockIdx.y;
    int n  = blockIdx.x * 32 + threadIdx.x;
    int ty = threadIdx.y;
    const float* xb = x + (size_t)b * CCH * NPIX + n;

    float s = 0.f, s2 = 0.f;
    for (int c = ty; c < CCH; c += 8) {
        float v = xb[(size_t)c * NPIX];
        s += v; s2 += v * v;
    }
    __shared__ float sh1[8][32], sh2[8][32];
    sh1[ty][threadIdx.x] = s;
    sh2[ty][threadIdx.x] = s2;
    __syncthreads();
    float S = 0.f, S2 = 0.f;
#pragma unroll
    for (int r = 0; r < 8; r++) { S += sh1[r][threadIdx.x]; S2 += sh2[r][threadIdx.x]; }
    float mean = S * (1.f / CCH);
    float var  = S2 * (1.f / CCH) - mean * mean;
    float rstd = rsqrtf(var + EPSLN);

    float* xo = xn + (size_t)b * CCH * NPIX + n;
    for (int c = ty; c < CCH; c += 8) {
        xo[(size_t)c * NPIX] = (xb[(size_t)c * NPIX] - mean) * rstd * gamma[c];
    }
}

// ---------------------------------------------------------------------------
// 2,6) C[b][m][n] = sum_k W[m][k] * X[b][k][n]  (+ optional residual R)
//    64x64x16 tiles, 256 threads, 4x4 microtile. N fixed = NPIX.
// ---------------------------------------------------------------------------
__global__ void gemm_wx(const float* __restrict__ W, const float* __restrict__ X,
                        float* __restrict__ C, const float* __restrict__ R,
                        int M, int K) {
    __shared__ float Ws[16][64];
    __shared__ float Xs[16][64];
    int bb = blockIdx.z;
    int m0 = blockIdx.y * 64, n0 = blockIdx.x * 64;
    const float* Wp = W + (size_t)m0 * K;
    const float* Xp = X + (size_t)bb * K * NPIX + n0;

    int t  = threadIdx.x;
    int tx = t & 15, ty = t >> 4;
    int wm = t >> 2, wk = (t & 3) << 2;   // W tile: [64 m][16 k] read along k
    int xk = t >> 4, xn = (t & 15) << 2;  // X tile: [16 k][64 n] read along n

    float acc[4][4] = {};
    for (int k0 = 0; k0 < K; k0 += 16) {
        float4 wv = *(const float4*)(Wp + (size_t)wm * K + k0 + wk);
        Ws[wk    ][wm] = wv.x;
        Ws[wk + 1][wm] = wv.y;
        Ws[wk + 2][wm] = wv.z;
        Ws[wk + 3][wm] = wv.w;
        *(float4*)&Xs[xk][xn] = *(const float4*)(Xp + (size_t)(k0 + xk) * NPIX + xn);
        __syncthreads();
#pragma unroll
        for (int kk = 0; kk < 16; kk++) {
            float4 a4 = *(const float4*)&Ws[kk][ty << 2];
            float4 b4 = *(const float4*)&Xs[kk][tx << 2];
            float ar[4] = {a4.x, a4.y, a4.z, a4.w};
            float br[4] = {b4.x, b4.y, b4.z, b4.w};
#pragma unroll
            for (int i = 0; i < 4; i++)
#pragma unroll
                for (int j = 0; j < 4; j++)
                    acc[i][j] += ar[i] * br[j];
        }
        __syncthreads();
    }
    size_t base = (size_t)bb * M * NPIX;
#pragma unroll
    for (int i = 0; i < 4; i++) {
        size_t rowi = base + (size_t)(m0 + (ty << 2) + i) * NPIX + n0 + (tx << 2);
        float4 o = make_float4(acc[i][0], acc[i][1], acc[i][2], acc[i][3]);
        if (R) {
            float4 rv = *(const float4*)(R + rowi);
            o.x += rv.x; o.y += rv.y; o.z += rv.z; o.w += rv.w;
        }
        *(float4*)(C + rowi) = o;
    }
}

// ---------------------------------------------------------------------------
// 3) sim[bh][i][j] = SCALE * sum_c q[c][i] * k[c][j]   (TN GEMM, K=64)
// ---------------------------------------------------------------------------
__global__ void gemm_qk() {
    __shared__ float As[16][64], Bs[16][64];
    int bh = blockIdx.z;
    int b = bh >> 3, h = bh & 7;
    const float* q = g_qkv + ((size_t)b * QKVC + (size_t)h * DH) * NPIX;
    const float* k = q + (size_t)512 * NPIX;
    float* Cp = g_sim + (size_t)bh * NPIX * NPIX;
    int i0 = blockIdx.y * 64, j0 = blockIdx.x * 64;

    int t  = threadIdx.x;
    int tx = t & 15, ty = t >> 4;
    int lr = t >> 4, lc = (t & 15) << 2;

    float acc[4][4] = {};
    for (int c0 = 0; c0 < DH; c0 += 16) {
        *(float4*)&As[lr][lc] = *(const float4*)(q + (size_t)(c0 + lr) * NPIX + i0 + lc);
        *(float4*)&Bs[lr][lc] = *(const float4*)(k + (size_t)(c0 + lr) * NPIX + j0 + lc);
        __syncthreads();
#pragma unroll
        for (int kk = 0; kk < 16; kk++) {
            float4 a4 = *(const float4*)&As[kk][ty << 2];
            float4 b4 = *(const float4*)&Bs[kk][tx << 2];
            float ar[4] = {a4.x, a4.y, a4.z, a4.w};
            float br[4] = {b4.x, b4.y, b4.z, b4.w};
#pragma unroll
            for (int i = 0; i < 4; i++)
#pragma unroll
                for (int j = 0; j < 4; j++)
                    acc[i][j] += ar[i] * br[j];
        }
        __syncthreads();
    }
#pragma unroll
    for (int i = 0; i < 4; i++) {
        size_t rowi = (size_t)(i0 + (ty << 2) + i) * NPIX + j0 + (tx << 2);
        float4 o = make_float4(acc[i][0] * SCALE, acc[i][1] * SCALE,
                               acc[i][2] * SCALE, acc[i][3] * SCALE);
        *(float4*)(Cp + rowi) = o;
    }
}

// ---------------------------------------------------------------------------
// 4) Row softmax over j (1024 contiguous). The reference ALPHA trick reduces
//    exactly to softmax(t - max(t)). One block of 128 threads per row.
// ---------------------------------------------------------------------------
__global__ void softmax_k() {
    size_t row = blockIdx.x;
    float* p = g_sim + row * NPIX;
    int t = threadIdx.x;

    float v[8];
    float mx = -1e30f;
#pragma unroll
    for (int r = 0; r < 8; r++) { v[r] = p[t + 128 * r]; mx = fmaxf(mx, v[r]); }
#pragma unroll
    for (int o = 16; o; o >>= 1) mx = fmaxf(mx, __shfl_xor_sync(0xffffffffu, mx, o));
    __shared__ float sm[4], ss[4];
    if ((t & 31) == 0) sm[t >> 5] = mx;
    __syncthreads();
    mx = fmaxf(fmaxf(sm[0], sm[1]), fmaxf(sm[2], sm[3]));

    float s = 0.f;
#pragma unroll
    for (int r = 0; r < 8; r++) { v[r] = __expf(v[r] - mx); s += v[r]; }
#pragma unroll
    for (int o = 16; o; o >>= 1) s += __shfl_xor_sync(0xffffffffu, s, o);
    if ((t & 31) == 0) ss[t >> 5] = s;
    __syncthreads();
    s = ss[0] + ss[1] + ss[2] + ss[3];
    float inv = 1.0f / s;
#pragma unroll
    for (int r = 0; r < 8; r++) p[t + 128 * r] = v[r] * inv;
}

// ---------------------------------------------------------------------------
// 5) O[bh][c][i] = sum_j V[c][j] * P[i][j]   (NT GEMM, M=64, K=1024)
// ---------------------------------------------------------------------------
__global__ void gemm_pv() {
    __shared__ float Vs[16][64], Ps[16][64];
    int bh = blockIdx.z;
    int b = bh >> 3, h = bh & 7;
    const float* V = g_qkv + ((size_t)b * QKVC + 1024 + (size_t)h * DH) * NPIX;
    const float* P = g_sim + (size_t)bh * NPIX * NPIX;
    float* O = g_att + ((size_t)b * CCH + (size_t)h * DH) * NPIX;
    int i0 = blockIdx.x * 64;

    int t  = threadIdx.x;
    int tx = t & 15, ty = t >> 4;
    int m = t >> 2, kq = (t & 3) << 2;

    float acc[4][4] = {};
    for (int k0 = 0; k0 < NPIX; k0 += 16) {
        float4 vv = *(const float4*)(V + (size_t)m * NPIX + k0 + kq);
        Vs[kq    ][m] = vv.x;
        Vs[kq + 1][m] = vv.y;
        Vs[kq + 2][m] = vv.z;
        Vs[kq + 3][m] = vv.w;
        float4 pv = *(const float4*)(P + (size_t)(i0 + m) * NPIX + k0 + kq);
        Ps[kq    ][m] = pv.x;
        Ps[kq + 1][m] = pv.y;
        Ps[kq + 2][m] = pv.z;
        Ps[kq + 3][m] = pv.w;
        __syncthreads();
#pragma unroll
        for (int kk = 0; kk < 16; kk++) {
            float4 a4 = *(const float4*)&Vs[kk][ty << 2];
            float4 b4 = *(const float4*)&Ps[kk][tx << 2];
            float ar[4] = {a4.x, a4.y, a4.z, a4.w};
            float br[4] = {b4.x, b4.y, b4.z, b4.w};
#pragma unroll
            for (int i = 0; i < 4; i++)
#pragma unroll
                for (int j = 0; j < 4; j++)
                    acc[i][j] += ar[i] * br[j];
        }
        __syncthreads();
    }
#pragma unroll
    for (int i = 0; i < 4; i++) {
        size_t rowi = (size_t)((ty << 2) + i) * NPIX + i0 + (tx << 2);
        float4 o = make_float4(acc[i][0], acc[i][1], acc[i][2], acc[i][3]);
        *(float4*)(O + rowi) = o;
    }
}

// ---------------------------------------------------------------------------
extern "C" void kernel_launch(void* const* d_in, const int* in_sizes, int n_in,
                              void* d_out, int out_size) {
    const float* x      = (const float*)d_in[0];
    const float* gamma  = (const float*)d_in[1];
    const float* w_qkv  = (const float*)d_in[2];
    const float* w_out  = (const float*)d_in[3];
    float* out = (float*)d_out;

    float *xn, *qkv, *att;
    cudaGetSymbolAddress((void**)&xn,  g_xn);
    cudaGetSymbolAddress((void**)&qkv, g_qkv);
    cudaGetSymbolAddress((void**)&att, g_att);

    // 1) LayerNorm over channels
    ln_kernel<<<dim3(NPIX / 32, BATCH), dim3(32, 8)>>>(x, gamma, xn);
    // 2) QKV projection: [1536x512] @ [512x1024] per batch
    gemm_wx<<<dim3(NPIX / 64, QKVC / 64, BATCH), 256>>>(w_qkv, xn, qkv, nullptr, QKVC, CCH);
    // 3) sim = SCALE * q^T k per (b,h)
    gemm_qk<<<dim3(NPIX / 64, NPIX / 64, BHTOT), 256>>>();
    // 4) softmax rows
    softmax_k<<<dim3(BHTOT * NPIX), 128>>>();
    // 5) O = V @ P^T per (b,h)
    gemm_pv<<<dim3(NPIX / 64, 1, BHTOT), 256>>>();
    // 6) out proj + residual
    gemm_wx<<<dim3(NPIX / 64, CCH / 64, BATCH), 256>>>(w_out, att, out, x, CCH, CCH);
}

// round 2
// speedup vs baseline: 1.1435x; 1.1435x over previous
#include <cuda_runtime.h>
#include <cuda_bf16.h>

#define BATCH 8
#define CCH   512
#define NPIX  1024
#define QKVC  1536
#define DH    64
#define BHTOT 64
#define EPSLN 1e-5f
#define SCALEF 0.125f

// Scratch (device globals: allocation-free contract)
__device__ float g_xn [(size_t)BATCH * CCH  * NPIX];   // normalized input [b][c][n]
__device__ float g_qkv[(size_t)BATCH * QKVC * NPIX];   // q:0-511 k:512-1023 v:1024-1535
__device__ float g_sim[(size_t)BHTOT * NPIX * NPIX];   // [bh][i][j]
__device__ float g_att[(size_t)BATCH * CCH  * NPIX];   // [b][h*64+c][n]

// ---------------------------------------------------------------------------
// tf32 helpers
// ---------------------------------------------------------------------------
__device__ __forceinline__ unsigned f2t(float f) {
    unsigned u; asm("cvt.rna.tf32.f32 %0, %1;" : "=r"(u) : "f"(f)); return u;
}
__device__ __forceinline__ void mma8(float* c, const unsigned* a, const unsigned* b) {
    asm volatile("mma.sync.aligned.m16n8k8.row.col.f32.tf32.tf32.f32 "
        "{%0,%1,%2,%3}, {%4,%5,%6,%7}, {%8,%9}, {%0,%1,%2,%3};"
        : "+f"(c[0]), "+f"(c[1]), "+f"(c[2]), "+f"(c[3])
        : "r"(a[0]), "r"(a[1]), "r"(a[2]), "r"(a[3]), "r"(b[0]), "r"(b[1]));
}

// Fragment-order smem offsets (A: m16k8 frag = 32 lanes x 4 regs; B: k8n8 = 32 x 2)
__device__ __forceinline__ int a_off(int m, int k) {
    return (((m >> 4) * 4 + (k >> 3)) * 32 + (m & 7) * 4 + (k & 3)) * 4
           + ((m >> 3) & 1) + 2 * ((k >> 2) & 1);
}
__device__ __forceinline__ int b_off(int k, int n) {
    return (((n >> 3) * 4 + (k >> 3)) * 32 + (n & 7) * 4 + (k & 3)) * 2
           + ((k >> 2) & 1);
}

// ---------------------------------------------------------------------------
// Generic TF32 tensor-core GEMM core.
//   C[m][n] = alpha * sum_k A(m,k) * B(k,n)  (+ R[m][n] if RES)
//   TA=0: A mem [M][K] (ldA=K-ish); TA=1: A mem [K][M]
//   TB=0: B mem [K][N];             TB=1: B mem [N][K]
//   BN fixed 64. BM in {64,128}. NT = 2*BM threads. All C/R row stride = NPIX.
// ---------------------------------------------------------------------------
template<int BM, int NT, bool TA, bool TB, bool RES>
__device__ __forceinline__ void gemm_core(
    const float* __restrict__ A, int ldA,
    const float* __restrict__ B, int ldB,
    float* __restrict__ C, const float* __restrict__ R,
    int K, float alpha)
{
    constexpr int BN = 64;
    __shared__ unsigned As[BM * 32];
    __shared__ unsigned Bs[BN * 32];
    const int tid  = threadIdx.x;
    const int lane = tid & 31, warp = tid >> 5;
    const int wm = warp >> 1, wn = warp & 1;
    const int m0 = blockIdx.y * BM, n0 = blockIdx.x * BN;

    constexpr int AF4 = BM * 32 / 4 / NT;   // float4 loads per thread for A
    constexpr int BF4 = BN * 32 / 4 / NT;

    float acc[2][4][4] = {};

    for (int k0 = 0; k0 < K; k0 += 32) {
#pragma unroll
        for (int it = 0; it < AF4; it++) {
            int idx = tid + it * NT;
            if constexpr (!TA) {
                int m = idx >> 3, k = (idx & 7) * 4;
                float4 v = *(const float4*)(A + (size_t)(m0 + m) * ldA + k0 + k);
                unsigned u[4] = {f2t(v.x), f2t(v.y), f2t(v.z), f2t(v.w)};
#pragma unroll
                for (int j = 0; j < 4; j++) As[a_off(m, k + j)] = u[j];
            } else {
                int k = idx / (BM / 4), m = (idx % (BM / 4)) * 4;
                float4 v = *(const float4*)(A + (size_t)(k0 + k) * ldA + m0 + m);
                unsigned u[4] = {f2t(v.x), f2t(v.y), f2t(v.z), f2t(v.w)};
#pragma unroll
                for (int j = 0; j < 4; j++) As[a_off(m + j, k)] = u[j];
            }
        }
#pragma unroll
        for (int it = 0; it < BF4; it++) {
            int idx = tid + it * NT;
            if constexpr (!TB) {
                int k = idx >> 4, n = (idx & 15) * 4;
                float4 v = *(const float4*)(B + (size_t)(k0 + k) * ldB + n0 + n);
                unsigned u[4] = {f2t(v.x), f2t(v.y), f2t(v.z), f2t(v.w)};
#pragma unroll
                for (int j = 0; j < 4; j++) Bs[b_off(k, n + j)] = u[j];
            } else {
                int n = idx >> 3, k = (idx & 7) * 4;
                float4 v = *(const float4*)(B + (size_t)(n0 + n) * ldB + k0 + k);
                unsigned u[4] = {f2t(v.x), f2t(v.y), f2t(v.z), f2t(v.w)};
#pragma unroll
                for (int j = 0; j < 4; j++) Bs[b_off(k + j, n)] = u[j];
            }
        }
        __syncthreads();
#pragma unroll
        for (int ks = 0; ks < 4; ks++) {
            unsigned a[2][4], b[4][2];
#pragma unroll
            for (int mfi = 0; mfi < 2; mfi++) {
                uint4 t = *(const uint4*)&As[(((wm * 2 + mfi) * 4 + ks) * 32 + lane) * 4];
                a[mfi][0] = t.x; a[mfi][1] = t.y; a[mfi][2] = t.z; a[mfi][3] = t.w;
            }
#pragma unroll
            for (int nfi = 0; nfi < 4; nfi++) {
                uint2 t = *(const uint2*)&Bs[(((wn * 4 + nfi) * 4 + ks) * 32 + lane) * 2];
                b[nfi][0] = t.x; b[nfi][1] = t.y;
            }
#pragma unroll
            for (int mfi = 0; mfi < 2; mfi++)
#pragma unroll
                for (int nfi = 0; nfi < 4; nfi++)
                    mma8(acc[mfi][nfi], a[mfi], b[nfi]);
        }
        __syncthreads();
    }

#pragma unroll
    for (int mfi = 0; mfi < 2; mfi++) {
#pragma unroll
        for (int nfi = 0; nfi < 4; nfi++) {
            int row = m0 + wm * 32 + mfi * 16 + (lane >> 2);
            int col = n0 + wn * 32 + nfi * 8 + (lane & 3) * 2;
            float2 v0 = make_float2(acc[mfi][nfi][0] * alpha, acc[mfi][nfi][1] * alpha);
            float2 v1 = make_float2(acc[mfi][nfi][2] * alpha, acc[mfi][nfi][3] * alpha);
            if constexpr (RES) {
                float2 r0 = *(const float2*)(R + (size_t)row * NPIX + col);
                float2 r1 = *(const float2*)(R + (size_t)(row + 8) * NPIX + col);
                v0.x += r0.x; v0.y += r0.y; v1.x += r1.x; v1.y += r1.y;
            }
            *(float2*)(C + (size_t)row * NPIX + col) = v0;
            *(float2*)(C + (size_t)(row + 8) * NPIX + col) = v1;
        }
    }
}

// ---------------------------------------------------------------------------
// 1) Channel LayerNorm over 512 channels per pixel
// ---------------------------------------------------------------------------
__global__ void ln_kernel(const float* __restrict__ x,
                          const float* __restrict__ gamma) {
    int b  = blockIdx.y;
    int n  = blockIdx.x * 32 + threadIdx.x;
    int ty = threadIdx.y;
    const float* xb = x + (size_t)b * CCH * NPIX + n;

    float s = 0.f, s2 = 0.f;
    for (int c = ty; c < CCH; c += 8) {
        float v = xb[(size_t)c * NPIX];
        s += v; s2 += v * v;
    }
    __shared__ float sh1[8][32], sh2[8][32];
    sh1[ty][threadIdx.x] = s;
    sh2[ty][threadIdx.x] = s2;
    __syncthreads();
    float S = 0.f, S2 = 0.f;
#pragma unroll
    for (int r = 0; r < 8; r++) { S += sh1[r][threadIdx.x]; S2 += sh2[r][threadIdx.x]; }
    float mean = S * (1.f / CCH);
    float var  = S2 * (1.f / CCH) - mean * mean;
    float rstd = rsqrtf(var + EPSLN);

    float* xo = g_xn + (size_t)b * CCH * NPIX + n;
    for (int c = ty; c < CCH; c += 8)
        xo[(size_t)c * NPIX] = (xb[(size_t)c * NPIX] - mean) * rstd * gamma[c];
}

// ---------------------------------------------------------------------------
// GEMM wrappers
// ---------------------------------------------------------------------------
__global__ void __launch_bounds__(256) k_qkv(const float* __restrict__ W) {
    int b = blockIdx.z;
    gemm_core<128, 256, false, false, false>(
        W, CCH,
        g_xn + (size_t)b * CCH * NPIX, NPIX,
        g_qkv + (size_t)b * QKVC * NPIX, nullptr, CCH, 1.f);
}

__global__ void __launch_bounds__(256) k_qk() {
    int bh = blockIdx.z, b = bh >> 3, h = bh & 7;
    const float* q = g_qkv + ((size_t)b * QKVC + (size_t)h * DH) * NPIX;
    gemm_core<128, 256, true, false, false>(
        q, NPIX,                       // A = q [c][i] -> TA=1
        q + (size_t)512 * NPIX, NPIX,  // B = k [c][j]
        g_sim + (size_t)bh * NPIX * NPIX, nullptr, DH, SCALEF);
}

__global__ void __launch_bounds__(128) k_pv() {
    int bh = blockIdx.z, b = bh >> 3, h = bh & 7;
    const float* v = g_qkv + ((size_t)b * QKVC + 1024 + (size_t)h * DH) * NPIX;
    gemm_core<64, 128, false, true, false>(
        v, NPIX,                                // A = V [c][j]
        g_sim + (size_t)bh * NPIX * NPIX, NPIX, // B = P [i][j] -> TB=1
        g_att + ((size_t)b * CCH + (size_t)h * DH) * NPIX, nullptr, NPIX, 1.f);
}

__global__ void __launch_bounds__(256) k_out(const float* __restrict__ W,
                                             const float* __restrict__ X,
                                             float* __restrict__ O) {
    int b = blockIdx.z;
    gemm_core<128, 256, false, false, true>(
        W, CCH,
        g_att + (size_t)b * CCH * NPIX, NPIX,
        O + (size_t)b * CCH * NPIX,
        X + (size_t)b * CCH * NPIX, CCH, 1.f);
}

// ---------------------------------------------------------------------------
// 4) Row softmax (ALPHA trick reduces exactly to stable softmax)
// ---------------------------------------------------------------------------
__global__ void softmax_k() {
    size_t row = blockIdx.x;
    float* p = g_sim + row * NPIX;
    int t = threadIdx.x;

    float v[8];
    float mx = -1e30f;
#pragma unroll
    for (int r = 0; r < 8; r++) { v[r] = p[t + 128 * r]; mx = fmaxf(mx, v[r]); }
#pragma unroll
    for (int o = 16; o; o >>= 1) mx = fmaxf(mx, __shfl_xor_sync(0xffffffffu, mx, o));
    __shared__ float sm[4], ss[4];
    if ((t & 31) == 0) sm[t >> 5] = mx;
    __syncthreads();
    mx = fmaxf(fmaxf(sm[0], sm[1]), fmaxf(sm[2], sm[3]));

    float s = 0.f;
#pragma unroll
    for (int r = 0; r < 8; r++) { v[r] = __expf(v[r] - mx); s += v[r]; }
#pragma unroll
    for (int o = 16; o; o >>= 1) s += __shfl_xor_sync(0xffffffffu, s, o);
    if ((t & 31) == 0) ss[t >> 5] = s;
    __syncthreads();
    s = ss[0] + ss[1] + ss[2] + ss[3];
    float inv = 1.0f / s;
#pragma unroll
    for (int r = 0; r < 8; r++) p[t + 128 * r] = v[r] * inv;
}

// ---------------------------------------------------------------------------
extern "C" void kernel_launch(void* const* d_in, const int* in_sizes, int n_in,
                              void* d_out, int out_size) {
    const float* x     = (const float*)d_in[0];
    const float* gamma = (const float*)d_in[1];
    const float* w_qkv = (const float*)d_in[2];
    const float* w_out = (const float*)d_in[3];
    float* out = (float*)d_out;

    ln_kernel<<<dim3(NPIX / 32, BATCH), dim3(32, 8)>>>(x, gamma);
    k_qkv<<<dim3(NPIX / 64, QKVC / 128, BATCH), 256>>>(w_qkv);
    k_qk <<<dim3(NPIX / 64, NPIX / 128, BHTOT), 256>>>();
    softmax_k<<<dim3(BHTOT * NPIX), 128>>>();
    k_pv <<<dim3(NPIX / 64, 1, BHTOT), 128>>>();
    k_out<<<dim3(NPIX / 64, CCH / 128, BATCH), 256>>>(w_out, x, out);
}

// round 7
// speedup vs baseline: 1.3789x; 1.2059x over previous
#include <cuda_runtime.h>
#include <cstdint>

#define BATCH 8
#define CCH   512
#define NPIX  1024
#define QKVC  1536
#define BHTOT 64
#define EPSLN 1e-5f
#define SCALEF 0.125f

// Scratch (device globals: allocation-free contract)
__device__ float g_xn [(size_t)BATCH * NPIX * CCH];   // [b][n][c]  (transposed LN out)
__device__ float g_qkv[(size_t)BATCH * QKVC * NPIX];  // [b][o][n]  q:0-511 k:512-1023 v:1024-1535
__device__ float g_sim[(size_t)BHTOT * NPIX * NPIX];  // [bh][i][j]
__device__ float g_att[(size_t)BATCH * NPIX * CCH];   // [b][n][c]  (O as [i][c])

// ---------------------------------------------------------------------------
// tf32 mma.sync helpers (validated in R2)
// ---------------------------------------------------------------------------
__device__ __forceinline__ unsigned f2t(float f) {
    unsigned u; asm("cvt.rna.tf32.f32 %0, %1;" : "=r"(u) : "f"(f)); return u;
}
__device__ __forceinline__ void mma8(float* c, const unsigned* a, const unsigned* b) {
    asm volatile("mma.sync.aligned.m16n8k8.row.col.f32.tf32.tf32.f32 "
        "{%0,%1,%2,%3}, {%4,%5,%6,%7}, {%8,%9}, {%0,%1,%2,%3};"
        : "+f"(c[0]), "+f"(c[1]), "+f"(c[2]), "+f"(c[3])
        : "r"(a[0]), "r"(a[1]), "r"(a[2]), "r"(a[3]), "r"(b[0]), "r"(b[1]));
}
// Fragment-order smem offsets (A: m16k8 frag = 32 lanes x 4 regs; B: k8n8 = 32 x 2)
__device__ __forceinline__ int a_off(int m, int k) {
    return (((m >> 4) * 4 + (k >> 3)) * 32 + (m & 7) * 4 + (k & 3)) * 4
           + ((m >> 3) & 1) + 2 * ((k >> 2) & 1);
}
__device__ __forceinline__ int b_off(int k, int n) {
    return (((n >> 3) * 4 + (k >> 3)) * 32 + (n & 7) * 4 + (k & 3)) * 2
           + ((k >> 2) & 1);
}

// ---------------------------------------------------------------------------
// TF32 tensor-core GEMM, 128x64 CTA tile, KC=32 chunks, register-prefetch
// double buffering. 256 threads, warp grid 4x2 (warp tile 32x32).
//   C[m][n] = alpha * sum_k A(m,k) * B(k,n)  (+R)
//   TA=0: A mem [M][K]; TA=1: A mem [K][M]
//   TB=0: B mem [K][N]; TB=1: B mem [N][K]
// ---------------------------------------------------------------------------
template<bool TA, bool TB, bool RES>
__device__ __forceinline__ void gemm_core(
    const float* __restrict__ A, int ldA,
    const float* __restrict__ B, int ldB,
    float* __restrict__ C, int ldC,
    const float* __restrict__ R,
    int K, float alpha)
{
    constexpr int BM = 128, BN = 64;
    __shared__ unsigned As[BM * 32];
    __shared__ unsigned Bs[BN * 32];
    const int tid  = threadIdx.x;
    const int lane = tid & 31, warp = tid >> 5;
    const int wm = warp >> 1, wn = warp & 1;           // 4x2 warps
    const int m0 = blockIdx.y * BM, n0 = blockIdx.x * BN;

    float4 pa[4], pb[2];

    auto loadA = [&](int k0) {
#pragma unroll
        for (int it = 0; it < 4; it++) {
            int idx = tid + it * 256;
            if constexpr (!TA) {
                int m = idx >> 3, kq = (idx & 7) * 4;
                pa[it] = *(const float4*)(A + (size_t)(m0 + m) * ldA + k0 + kq);
            } else {
                int k = idx >> 5, mq = (idx & 31) * 4;
                pa[it] = *(const float4*)(A + (size_t)(k0 + k) * ldA + m0 + mq);
            }
        }
    };
    auto loadB = [&](int k0) {
#pragma unroll
        for (int it = 0; it < 2; it++) {
            int idx = tid + it * 256;
            if constexpr (TB) {
                int n = idx >> 3, kq = (idx & 7) * 4;
                pb[it] = *(const float4*)(B + (size_t)(n0 + n) * ldB + k0 + kq);
            } else {
                int k = idx >> 4, nq = (idx & 15) * 4;
                pb[it] = *(const float4*)(B + (size_t)(k0 + k) * ldB + n0 + nq);
            }
        }
    };
    auto stage = [&]() {
#pragma unroll
        for (int it = 0; it < 4; it++) {
            int idx = tid + it * 256;
            unsigned u[4] = {f2t(pa[it].x), f2t(pa[it].y), f2t(pa[it].z), f2t(pa[it].w)};
            if constexpr (!TA) {
                int m = idx >> 3, kq = (idx & 7) * 4;
#pragma unroll
                for (int j = 0; j < 4; j++) As[a_off(m, kq + j)] = u[j];
            } else {
                int k = idx >> 5, mq = (idx & 31) * 4;
#pragma unroll
                for (int j = 0; j < 4; j++) As[a_off(mq + j, k)] = u[j];
            }
        }
#pragma unroll
        for (int it = 0; it < 2; it++) {
            int idx = tid + it * 256;
            unsigned u[4] = {f2t(pb[it].x), f2t(pb[it].y), f2t(pb[it].z), f2t(pb[it].w)};
            if constexpr (TB) {
                int n = idx >> 3, kq = (idx & 7) * 4;
#pragma unroll
                for (int j = 0; j < 4; j++) Bs[b_off(kq + j, n)] = u[j];
            } else {
                int k = idx >> 4, nq = (idx & 15) * 4;
#pragma unroll
                for (int j = 0; j < 4; j++) Bs[b_off(k, nq + j)] = u[j];
            }
        }
    };

    float acc[2][4][4] = {};
    loadA(0); loadB(0);

    for (int k0 = 0; k0 < K; k0 += 32) {
        stage();
        __syncthreads();
        if (k0 + 32 < K) { loadA(k0 + 32); loadB(k0 + 32); }  // overlap with compute
#pragma unroll
        for (int ks = 0; ks < 4; ks++) {
            unsigned a[2][4], b[4][2];
#pragma unroll
            for (int mfi = 0; mfi < 2; mfi++) {
                uint4 t = *(const uint4*)&As[(((wm * 2 + mfi) * 4 + ks) * 32 + lane) * 4];
                a[mfi][0] = t.x; a[mfi][1] = t.y; a[mfi][2] = t.z; a[mfi][3] = t.w;
            }
#pragma unroll
            for (int nfi = 0; nfi < 4; nfi++) {
                uint2 t = *(const uint2*)&Bs[(((wn * 4 + nfi) * 4 + ks) * 32 + lane) * 2];
                b[nfi][0] = t.x; b[nfi][1] = t.y;
            }
#pragma unroll
            for (int mfi = 0; mfi < 2; mfi++)
#pragma unroll
                for (int nfi = 0; nfi < 4; nfi++)
                    mma8(acc[mfi][nfi], a[mfi], b[nfi]);
        }
        __syncthreads();
    }

#pragma unroll
    for (int mfi = 0; mfi < 2; mfi++) {
#pragma unroll
        for (int nfi = 0; nfi < 4; nfi++) {
            int row = m0 + wm * 32 + mfi * 16 + (lane >> 2);
            int col = n0 + wn * 32 + nfi * 8 + (lane & 3) * 2;
            float2 v0 = make_float2(acc[mfi][nfi][0] * alpha, acc[mfi][nfi][1] * alpha);
            float2 v1 = make_float2(acc[mfi][nfi][2] * alpha, acc[mfi][nfi][3] * alpha);
            if constexpr (RES) {
                float2 r0 = *(const float2*)(R + (size_t)row * ldC + col);
                float2 r1 = *(const float2*)(R + (size_t)(row + 8) * ldC + col);
                v0.x += r0.x; v0.y += r0.y; v1.x += r1.x; v1.y += r1.y;
            }
            *(float2*)(C + (size_t)row * ldC + col) = v0;
            *(float2*)(C + (size_t)(row + 8) * ldC + col) = v1;
        }
    }
}

// ---------------------------------------------------------------------------
// GEMM wrappers
// ---------------------------------------------------------------------------
__global__ void __launch_bounds__(256, 2) k_qkv(const float* __restrict__ W) {
    int b = blockIdx.z;
    gemm_core<false, true, false>(W, CCH,
        g_xn + (size_t)b * NPIX * CCH, CCH,                 // B = xn [n][c] (TB=1)
        g_qkv + (size_t)b * QKVC * NPIX, NPIX, nullptr, CCH, 1.f);
}
__global__ void __launch_bounds__(256, 2) k_qk() {
    int bh = blockIdx.z, b = bh >> 3, h = bh & 7;
    const float* q = g_qkv + ((size_t)b * QKVC + (size_t)h * 64) * NPIX;
    gemm_core<true, false, false>(q, NPIX,                  // A = q [c][i] (TA=1)
        q + (size_t)512 * NPIX, NPIX,                       // B = k [c][j]
        g_sim + (size_t)bh * NPIX * NPIX, NPIX, nullptr, 64, SCALEF);
}
__global__ void __launch_bounds__(256, 2) k_pv() {
    int bh = blockIdx.z, b = bh >> 3, h = bh & 7;
    gemm_core<false, true, false>(
        g_sim + (size_t)bh * NPIX * NPIX, NPIX,             // A = P [i][j]
        g_qkv + ((size_t)b * QKVC + 1024 + (size_t)h * 64) * NPIX, NPIX, // B = V [c][j] (TB=1)
        g_att + (size_t)b * NPIX * CCH + (size_t)h * 64, CCH, nullptr, NPIX, 1.f);
}
__global__ void __launch_bounds__(256, 2) k_out(const float* __restrict__ W,
                                                const float* __restrict__ X,
                                                float* __restrict__ O) {
    int b = blockIdx.z;
    gemm_core<false, true, true>(W, CCH,
        g_att + (size_t)b * NPIX * CCH, CCH,                // B = att [n][c] (TB=1)
        O + (size_t)b * CCH * NPIX, NPIX,
        X + (size_t)b * CCH * NPIX, CCH, 1.f);
}

// ---------------------------------------------------------------------------
// Channel LayerNorm; writes g_xn transposed [b][n][c] via smem tile.
// ---------------------------------------------------------------------------
__global__ void ln_kernel(const float* __restrict__ x, const float* __restrict__ gamma) {
    int b = blockIdx.y, n0 = blockIdx.x * 32;
    int tx = threadIdx.x, ty = threadIdx.y;
    const float* xb = x + (size_t)b * CCH * NPIX + n0 + tx;

    float s = 0.f, s2 = 0.f;
    for (int c = ty; c < CCH; c += 8) {
        float v = xb[(size_t)c * NPIX];
        s += v; s2 += v * v;
    }
    __shared__ float sh1[8][32], sh2[8][32];
    sh1[ty][tx] = s; sh2[ty][tx] = s2;
    __syncthreads();
    float S = 0.f, S2 = 0.f;
#pragma unroll
    for (int r = 0; r < 8; r++) { S += sh1[r][tx]; S2 += sh2[r][tx]; }
    float mean = S * (1.f / CCH);
    float var  = S2 * (1.f / CCH) - mean * mean;
    float rstd = rsqrtf(var + EPSLN);

    __shared__ float tile[32][72];
    float* xo = g_xn + (size_t)b * NPIX * CCH;
    int tid = ty * 32 + tx;
    for (int c0 = 0; c0 < CCH; c0 += 64) {
#pragma unroll
        for (int j = 0; j < 8; j++) {
            int c = c0 + ty * 8 + j;
            tile[tx][ty * 8 + j] = (xb[(size_t)c * NPIX] - mean) * rstd * gamma[c];
        }
        __syncthreads();
        int row = tid >> 3, cq = (tid & 7) * 8;
        float4 a = *(float4*)&tile[row][cq];
        float4 bq = *(float4*)&tile[row][cq + 4];
        *(float4*)(xo + (size_t)(n0 + row) * CCH + c0 + cq) = a;
        *(float4*)(xo + (size_t)(n0 + row) * CCH + c0 + cq + 4) = bq;
        __syncthreads();
    }
}

// ---------------------------------------------------------------------------
// Row softmax (ALPHA trick reduces exactly to stable softmax)
// ---------------------------------------------------------------------------
__global__ void softmax_k() {
    size_t row = blockIdx.x;
    float* p = g_sim + row * NPIX;
    int t = threadIdx.x;

    float v[8];
    float mx = -1e30f;
#pragma unroll
    for (int r = 0; r < 8; r++) { v[r] = p[t + 128 * r]; mx = fmaxf(mx, v[r]); }
#pragma unroll
    for (int o = 16; o; o >>= 1) mx = fmaxf(mx, __shfl_xor_sync(0xffffffffu, mx, o));
    __shared__ float sm[4], ss[4];
    if ((t & 31) == 0) sm[t >> 5] = mx;
    __syncthreads();
    mx = fmaxf(fmaxf(sm[0], sm[1]), fmaxf(sm[2], sm[3]));

    float s = 0.f;
#pragma unroll
    for (int r = 0; r < 8; r++) { v[r] = __expf(v[r] - mx); s += v[r]; }
#pragma unroll
    for (int o = 16; o; o >>= 1) s += __shfl_xor_sync(0xffffffffu, s, o);
    if ((t & 31) == 0) ss[t >> 5] = s;
    __syncthreads();
    s = ss[0] + ss[1] + ss[2] + ss[3];
    float inv = 1.0f / s;
#pragma unroll
    for (int r = 0; r < 8; r++) p[t + 128 * r] = v[r] * inv;
}

// ---------------------------------------------------------------------------
extern "C" void kernel_launch(void* const* d_in, const int* in_sizes, int n_in,
                              void* d_out, int out_size) {
    const float* x     = (const float*)d_in[0];
    const float* gamma = (const float*)d_in[1];
    const float* w_qkv = (const float*)d_in[2];
    const float* w_out = (const float*)d_in[3];
    float* out = (float*)d_out;

    ln_kernel<<<dim3(NPIX / 32, BATCH), dim3(32, 8)>>>(x, gamma);
    k_qkv<<<dim3(NPIX / 64, QKVC / 128, BATCH), 256>>>(w_qkv);
    k_qk <<<dim3(NPIX / 64, NPIX / 128, BHTOT), 256>>>();
    softmax_k<<<dim3(BHTOT * NPIX), 128>>>();
    k_pv <<<dim3(1, NPIX / 128, BHTOT), 256>>>();
    k_out<<<dim3(NPIX / 64, CCH / 128, BATCH), 256>>>(w_out, x, out);
}

// round 10
// speedup vs baseline: 1.9022x; 1.3794x over previous
#include <cuda_runtime.h>
#include <cuda_fp16.h>
#include <cstdint>

#define BATCH 8
#define CCH   512
#define NPIX  1024
#define QKVC  1536
#define BHTOT 64
#define EPSLN 1e-5f
#define SCALEF 0.125f

// Scratch (device globals: allocation-free contract)
__device__ float g_xn [(size_t)BATCH * NPIX * CCH];   // [b][n][c]  (transposed LN out)
__device__ float g_qkv[(size_t)BATCH * QKVC * NPIX];  // [b][o][n]  q:0-511 k:512-1023 v:1024-1535
__device__ float g_sim[(size_t)BHTOT * NPIX * NPIX];  // [bh][i][j]
__device__ float g_att[(size_t)BATCH * NPIX * CCH];   // [b][n][c]  (O as [i][c])

// ---------------------------------------------------------------------------
// fp16 mma.sync helpers
// ---------------------------------------------------------------------------
__device__ __forceinline__ unsigned f2h2(float a, float b) {
    __half2 h = __floats2half2_rn(a, b);
    return *(unsigned*)&h;
}
__device__ __forceinline__ void mma16(float* c, const unsigned* a, const unsigned* b) {
    asm volatile("mma.sync.aligned.m16n8k16.row.col.f32.f16.f16.f32 "
        "{%0,%1,%2,%3}, {%4,%5,%6,%7}, {%8,%9}, {%0,%1,%2,%3};"
        : "+f"(c[0]), "+f"(c[1]), "+f"(c[2]), "+f"(c[3])
        : "r"(a[0]), "r"(a[1]), "r"(a[2]), "r"(a[3]), "r"(b[0]), "r"(b[1]));
}

// Fragment-order smem offsets, in uint (=half2) units.
// A frag m16k16 = 32 lanes x 4 uints; tile 128x32 -> 8 mtiles x 2 ktiles.
__device__ __forceinline__ int a_off(int m, int k) {
    return (((m >> 4) * 2 + (k >> 4)) * 32 + (m & 7) * 4 + ((k & 7) >> 1)) * 4
           + ((m >> 3) & 1) + 2 * ((k >> 3) & 1);
}
// B frag k16n8 = 32 lanes x 2 uints; tile 64x32 -> 8 ntiles x 2 ktiles.
__device__ __forceinline__ int b_off(int k, int n) {
    return (((n >> 3) * 2 + (k >> 4)) * 32 + (n & 7) * 4 + ((k & 7) >> 1)) * 2
           + ((k >> 3) & 1);
}

// ---------------------------------------------------------------------------
// FP16 tensor-core GEMM, 128x64 CTA tile, KC=32 chunks, register-prefetch
// double buffering. 256 threads, warp grid 4x2 (warp tile 32x32).
//   C[m][n] = alpha * sum_k A(m,k) * B(k,n)  (+R)
//   TA=0: A mem [M][K]; TA=1: A mem [K][M]
//   TB=0: B mem [K][N]; TB=1: B mem [N][K]
// ---------------------------------------------------------------------------
template<bool TA, bool TB, bool RES>
__device__ __forceinline__ void gemm_core(
    const float* __restrict__ A, int ldA,
    const float* __restrict__ B, int ldB,
    float* __restrict__ C, int ldC,
    const float* __restrict__ R,
    int K, float alpha)
{
    __shared__ unsigned As[128 * 32 / 2];   // 8KB (half2 units)
    __shared__ unsigned Bs[64 * 32 / 2];    // 4KB
    __half* Ah = (__half*)As;
    __half* Bh = (__half*)Bs;
    const int tid  = threadIdx.x;
    const int lane = tid & 31, warp = tid >> 5;
    const int wm = warp >> 1, wn = warp & 1;           // 4x2 warps
    const int m0 = blockIdx.y * 128, n0 = blockIdx.x * 64;

    float4 pa[4], pb[2];

    auto loadA = [&](int k0) {
#pragma unroll
        for (int it = 0; it < 4; it++) {
            int idx = tid + it * 256;
            if constexpr (!TA) {
                int m = idx >> 3, kq = (idx & 7) * 4;
                pa[it] = *(const float4*)(A + (size_t)(m0 + m) * ldA + k0 + kq);
            } else {
                int k = idx >> 5, mq = (idx & 31) * 4;
                pa[it] = *(const float4*)(A + (size_t)(k0 + k) * ldA + m0 + mq);
            }
        }
    };
    auto loadB = [&](int k0) {
#pragma unroll
        for (int it = 0; it < 2; it++) {
            int idx = tid + it * 256;
            if constexpr (TB) {
                int n = idx >> 3, kq = (idx & 7) * 4;
                pb[it] = *(const float4*)(B + (size_t)(n0 + n) * ldB + k0 + kq);
            } else {
                int k = idx >> 4, nq = (idx & 15) * 4;
                pb[it] = *(const float4*)(B + (size_t)(k0 + k) * ldB + n0 + nq);
            }
        }
    };
    auto stage = [&]() {
#pragma unroll
        for (int it = 0; it < 4; it++) {
            int idx = tid + it * 256;
            if constexpr (!TA) {
                int m = idx >> 3, kq = (idx & 7) * 4;
                As[a_off(m, kq)]     = f2h2(pa[it].x, pa[it].y);
                As[a_off(m, kq + 2)] = f2h2(pa[it].z, pa[it].w);
            } else {
                int k = idx >> 5, mq = (idx & 31) * 4;
                Ah[a_off(mq + 0, k) * 2 + (k & 1)] = __float2half_rn(pa[it].x);
                Ah[a_off(mq + 1, k) * 2 + (k & 1)] = __float2half_rn(pa[it].y);
                Ah[a_off(mq + 2, k) * 2 + (k & 1)] = __float2half_rn(pa[it].z);
                Ah[a_off(mq + 3, k) * 2 + (k & 1)] = __float2half_rn(pa[it].w);
            }
        }
#pragma unroll
        for (int it = 0; it < 2; it++) {
            int idx = tid + it * 256;
            if constexpr (TB) {
                int n = idx >> 3, kq = (idx & 7) * 4;
                Bs[b_off(kq, n)]     = f2h2(pb[it].x, pb[it].y);
                Bs[b_off(kq + 2, n)] = f2h2(pb[it].z, pb[it].w);
            } else {
                int k = idx >> 4, nq = (idx & 15) * 4;
                Bh[b_off(k, nq + 0) * 2 + (k & 1)] = __float2half_rn(pb[it].x);
                Bh[b_off(k, nq + 1) * 2 + (k & 1)] = __float2half_rn(pb[it].y);
                Bh[b_off(k, nq + 2) * 2 + (k & 1)] = __float2half_rn(pb[it].z);
                Bh[b_off(k, nq + 3) * 2 + (k & 1)] = __float2half_rn(pb[it].w);
            }
        }
    };

    float acc[2][4][4] = {};
    loadA(0); loadB(0);

    for (int k0 = 0; k0 < K; k0 += 32) {
        stage();
        __syncthreads();
        if (k0 + 32 < K) { loadA(k0 + 32); loadB(k0 + 32); }  // overlap with compute
#pragma unroll
        for (int ks = 0; ks < 2; ks++) {
            unsigned a[2][4], b[4][2];
#pragma unroll
            for (int mfi = 0; mfi < 2; mfi++) {
                uint4 t = *(const uint4*)&As[(((wm * 2 + mfi) * 2 + ks) * 32 + lane) * 4];
                a[mfi][0] = t.x; a[mfi][1] = t.y; a[mfi][2] = t.z; a[mfi][3] = t.w;
            }
#pragma unroll
            for (int nfi = 0; nfi < 4; nfi++) {
                uint2 t = *(const uint2*)&Bs[(((wn * 4 + nfi) * 2 + ks) * 32 + lane) * 2];
                b[nfi][0] = t.x; b[nfi][1] = t.y;
            }
#pragma unroll
            for (int mfi = 0; mfi < 2; mfi++)
#pragma unroll
                for (int nfi = 0; nfi < 4; nfi++)
                    mma16(acc[mfi][nfi], a[mfi], b[nfi]);
        }
        __syncthreads();
    }

#pragma unroll
    for (int mfi = 0; mfi < 2; mfi++) {
#pragma unroll
        for (int nfi = 0; nfi < 4; nfi++) {
            int row = m0 + wm * 32 + mfi * 16 + (lane >> 2);
            int col = n0 + wn * 32 + nfi * 8 + (lane & 3) * 2;
            float2 v0 = make_float2(acc[mfi][nfi][0] * alpha, acc[mfi][nfi][1] * alpha);
            float2 v1 = make_float2(acc[mfi][nfi][2] * alpha, acc[mfi][nfi][3] * alpha);
            if constexpr (RES) {
                float2 r0 = *(const float2*)(R + (size_t)row * ldC + col);
                float2 r1 = *(const float2*)(R + (size_t)(row + 8) * ldC + col);
                v0.x += r0.x; v0.y += r0.y; v1.x += r1.x; v1.y += r1.y;
            }
            *(float2*)(C + (size_t)row * ldC + col) = v0;
            *(float2*)(C + (size_t)(row + 8) * ldC + col) = v1;
        }
    }
}

// ---------------------------------------------------------------------------
// GEMM wrappers
// ---------------------------------------------------------------------------
__global__ void __launch_bounds__(256, 2) k_qkv(const float* __restrict__ W) {
    int b = blockIdx.z;
    gemm_core<false, true, false>(W, CCH,
        g_xn + (size_t)b * NPIX * CCH, CCH,                 // B = xn [n][c] (TB=1)
        g_qkv + (size_t)b * QKVC * NPIX, NPIX, nullptr, CCH, 1.f);
}
__global__ void __launch_bounds__(256, 2) k_qk() {
    int bh = blockIdx.z, b = bh >> 3, h = bh & 7;
    const float* q = g_qkv + ((size_t)b * QKVC + (size_t)h * 64) * NPIX;
    gemm_core<true, false, false>(q, NPIX,                  // A = q [c][i] (TA=1)
        q + (size_t)512 * NPIX, NPIX,                       // B = k [c][j]
        g_sim + (size_t)bh * NPIX * NPIX, NPIX, nullptr, 64, SCALEF);
}
__global__ void __launch_bounds__(256, 2) k_pv() {
    int bh = blockIdx.z, b = bh >> 3, h = bh & 7;
    gemm_core<false, true, false>(
        g_sim + (size_t)bh * NPIX * NPIX, NPIX,             // A = P [i][j]
        g_qkv + ((size_t)b * QKVC + 1024 + (size_t)h * 64) * NPIX, NPIX, // B = V [c][j] (TB=1)
        g_att + (size_t)b * NPIX * CCH + (size_t)h * 64, CCH, nullptr, NPIX, 1.f);
}
__global__ void __launch_bounds__(256, 2) k_out(const float* __restrict__ W,
                                                const float* __restrict__ X,
                                                float* __restrict__ O) {
    int b = blockIdx.z;
    gemm_core<false, true, true>(W, CCH,
        g_att + (size_t)b * NPIX * CCH, CCH,                // B = att [n][c] (TB=1)
        O + (size_t)b * CCH * NPIX, NPIX,
        X + (size_t)b * CCH * NPIX, CCH, 1.f);
}

// ---------------------------------------------------------------------------
// Channel LayerNorm; writes g_xn transposed [b][n][c] via smem tile.
// ---------------------------------------------------------------------------
__global__ void ln_kernel(const float* __restrict__ x, const float* __restrict__ gamma) {
    int b = blockIdx.y, n0 = blockIdx.x * 32;
    int tx = threadIdx.x, ty = threadIdx.y;
    const float* xb = x + (size_t)b * CCH * NPIX + n0 + tx;

    float s = 0.f, s2 = 0.f;
    for (int c = ty; c < CCH; c += 8) {
        float v = xb[(size_t)c * NPIX];
        s += v; s2 += v * v;
    }
    __shared__ float sh1[8][32], sh2[8][32];
    sh1[ty][tx] = s; sh2[ty][tx] = s2;
    __syncthreads();
    float S = 0.f, S2 = 0.f;
#pragma unroll
    for (int r = 0; r < 8; r++) { S += sh1[r][tx]; S2 += sh2[r][tx]; }
    float mean = S * (1.f / CCH);
    float var  = S2 * (1.f / CCH) - mean * mean;
    float rstd = rsqrtf(var + EPSLN);

    __shared__ float tile[32][72];
    float* xo = g_xn + (size_t)b * NPIX * CCH;
    int tid = ty * 32 + tx;
    for (int c0 = 0; c0 < CCH; c0 += 64) {
#pragma unroll
        for (int j = 0; j < 8; j++) {
            int c = c0 + ty * 8 + j;
            tile[tx][ty * 8 + j] = (xb[(size_t)c * NPIX] - mean) * rstd * gamma[c];
        }
        __syncthreads();
        int row = tid >> 3, cq = (tid & 7) * 8;
        float4 a = *(float4*)&tile[row][cq];
        float4 bq = *(float4*)&tile[row][cq + 4];
        *(float4*)(xo + (size_t)(n0 + row) * CCH + c0 + cq) = a;
        *(float4*)(xo + (size_t)(n0 + row) * CCH + c0 + cq + 4) = bq;
        __syncthreads();
    }
}

// ---------------------------------------------------------------------------
// Row softmax (ALPHA trick reduces exactly to stable softmax)
// ---------------------------------------------------------------------------
__global__ void softmax_k() {
    size_t row = blockIdx.x;
    float* p = g_sim + row * NPIX;
    int t = threadIdx.x;

    float v[8];
    float mx = -1e30f;
#pragma unroll
    for (int r = 0; r < 8; r++) { v[r] = p[t + 128 * r]; mx = fmaxf(mx, v[r]); }
#pragma unroll
    for (int o = 16; o; o >>= 1) mx = fmaxf(mx, __shfl_xor_sync(0xffffffffu, mx, o));
    __shared__ float sm[4], ss[4];
    if ((t & 31) == 0) sm[t >> 5] = mx;
    __syncthreads();
    mx = fmaxf(fmaxf(sm[0], sm[1]), fmaxf(sm[2], sm[3]));

    float s = 0.f;
#pragma unroll
    for (int r = 0; r < 8; r++) { v[r] = __expf(v[r] - mx); s += v[r]; }
#pragma unroll
    for (int o = 16; o; o >>= 1) s += __shfl_xor_sync(0xffffffffu, s, o);
    if ((t & 31) == 0) ss[t >> 5] = s;
    __syncthreads();
    s = ss[0] + ss[1] + ss[2] + ss[3];
    float inv = 1.0f / s;
#pragma unroll
    for (int r = 0; r < 8; r++) p[t + 128 * r] = v[r] * inv;
}

// ---------------------------------------------------------------------------
extern "C" void kernel_launch(void* const* d_in, const int* in_sizes, int n_in,
                              void* d_out, int out_size) {
    const float* x     = (const float*)d_in[0];
    const float* gamma = (const float*)d_in[1];
    const float* w_qkv = (const float*)d_in[2];
    const float* w_out = (const float*)d_in[3];
    float* out = (float*)d_out;

    ln_kernel<<<dim3(NPIX / 32, BATCH), dim3(32, 8)>>>(x, gamma);
    k_qkv<<<dim3(NPIX / 64, QKVC / 128, BATCH), 256>>>(w_qkv);
    k_qk <<<dim3(NPIX / 64, NPIX / 128, BHTOT), 256>>>();
    softmax_k<<<dim3(BHTOT * NPIX), 128>>>();
    k_pv <<<dim3(1, NPIX / 128, BHTOT), 256>>>();
    k_out<<<dim3(NPIX / 64, CCH / 128, BATCH), 256>>>(w_out, x, out);
}

// round 12
// speedup vs baseline: 2.7400x; 1.4405x over previous
#include <cuda_runtime.h>
#include <cuda_fp16.h>
#include <cstdint>

#define BATCH 8
#define CCH   512
#define NPIX  1024
#define QKVC  1536
#define BHTOT 64
#define EPSLN 1e-5f
#define SCALEF 0.125f

// Scratch (device globals: allocation-free contract)
__device__ __half g_xnh [(size_t)BATCH * NPIX * CCH];   // [b][n][c]  LN out (half)
__device__ __half g_qkvt[(size_t)BATCH * NPIX * QKVC];  // [b][n][o]  qkv^T (half)
__device__ float  g_sim [(size_t)BHTOT * NPIX * NPIX];  // [bh][i][j] logits (f32)
__device__ __half g_ph  [(size_t)BHTOT * NPIX * NPIX];  // [bh][i][j] probs (half)
__device__ __half g_atth[(size_t)BATCH * NPIX * CCH];   // [b][n][hc] attn out (half)
__device__ __half g_wqkvh[QKVC * CCH];
__device__ __half g_wouth[CCH * CCH];

// ---------------------------------------------------------------------------
// fp16 mma.sync helpers (fragment maps validated R10 on hardware)
// ---------------------------------------------------------------------------
__device__ __forceinline__ void mma16(float* c, const unsigned* a, const unsigned* b) {
    asm volatile("mma.sync.aligned.m16n8k16.row.col.f32.f16.f16.f32 "
        "{%0,%1,%2,%3}, {%4,%5,%6,%7}, {%8,%9}, {%0,%1,%2,%3};"
        : "+f"(c[0]), "+f"(c[1]), "+f"(c[2]), "+f"(c[3])
        : "r"(a[0]), "r"(a[1]), "r"(a[2]), "r"(a[3]), "r"(b[0]), "r"(b[1]));
}
// A frag m16k16, uint(half2) units. Tile rows x 32k -> (m>>4) mtiles x 2 ktiles.
__device__ __forceinline__ int a_off(int m, int k) {
    return (((m >> 4) * 2 + (k >> 4)) * 32 + (m & 7) * 4 + ((k & 7) >> 1)) * 4
           + ((m >> 3) & 1) + 2 * ((k >> 3) & 1);
}
// B frag k16n8.
__device__ __forceinline__ int b_off(int k, int n) {
    return (((n >> 3) * 2 + (k >> 4)) * 32 + (n & 7) * 4 + ((k & 7) >> 1)) * 2
           + ((k >> 3) & 1);
}

// ---------------------------------------------------------------------------
// FP16 tensor GEMM: 128 x BN CTA tile, KC=32 chunks, ping-pong smem (1 sync
// per chunk) + register prefetch. 256 threads, warps 4x2, warp tile 32x(BN/2).
//   C[m][n] = alpha * sum_k A(m,k) * B(k,n)  (+R if RES)
//   A: mem [M][K] half (k-contig). B: TB0=0 -> mem [N][K]; TB0=1 -> mem [K][N].
//   OH: C is half; else C is float.
// ---------------------------------------------------------------------------
template<int BN, bool TB0, bool OH, bool RES>
__device__ __forceinline__ void gemm16(
    const __half* __restrict__ A, int ldA,
    const __half* __restrict__ B, int ldB,
    void* __restrict__ Cv, int ldC,
    const float* __restrict__ R,
    int K, float alpha)
{
    constexpr int NFRAG = BN / 16;          // n-frags per warp
    __shared__ unsigned As[2][128 * 16];
    __shared__ unsigned Bs[2][BN * 16];
    const int tid  = threadIdx.x;
    const int lane = tid & 31, warp = tid >> 5;
    const int wm = warp >> 1, wn = warp & 1;
    const int m0 = blockIdx.y * 128, n0 = blockIdx.x * BN;

    uint4 pa[2], pb[2];
    constexpr int BIT = (BN * 32 / 8) / 256;  // uint4 B loads per thread (1 or 2)

    auto loadA = [&](int k0) {
#pragma unroll
        for (int it = 0; it < 2; it++) {
            int idx = tid + it * 256;
            int m = idx >> 2, kq = (idx & 3) * 8;
            pa[it] = *(const uint4*)(A + (size_t)(m0 + m) * ldA + k0 + kq);
        }
    };
    auto loadB = [&](int k0) {
#pragma unroll
        for (int it = 0; it < BIT; it++) {
            int idx = tid + it * 256;
            if constexpr (!TB0) {
                int n = idx >> 2, kq = (idx & 3) * 8;
                pb[it] = *(const uint4*)(B + (size_t)(n0 + n) * ldB + k0 + kq);
            } else {
                int k = idx >> 3, nq = (idx & 7) * 8;
                pb[it] = *(const uint4*)(B + (size_t)(k0 + k) * ldB + n0 + nq);
            }
        }
    };
    auto stage = [&](int p) {
#pragma unroll
        for (int it = 0; it < 2; it++) {
            int idx = tid + it * 256;
            int m = idx >> 2, kq = (idx & 3) * 8;
            unsigned u[4] = {pa[it].x, pa[it].y, pa[it].z, pa[it].w};
#pragma unroll
            for (int j = 0; j < 4; j++) As[p][a_off(m, kq + 2 * j)] = u[j];
        }
#pragma unroll
        for (int it = 0; it < BIT; it++) {
            int idx = tid + it * 256;
            if constexpr (!TB0) {
                int n = idx >> 2, kq = (idx & 3) * 8;
                unsigned u[4] = {pb[it].x, pb[it].y, pb[it].z, pb[it].w};
#pragma unroll
                for (int j = 0; j < 4; j++) Bs[p][b_off(kq + 2 * j, n)] = u[j];
            } else {
                int k = idx >> 3, nq = (idx & 7) * 8;
                __half h[8];
                *(uint4*)h = pb[it];
                __half* Bh = (__half*)Bs[p];
#pragma unroll
                for (int j = 0; j < 8; j++)
                    Bh[b_off(k, nq + j) * 2 + (k & 1)] = h[j];
            }
        }
    };

    float acc[2][NFRAG][4] = {};
    int p = 0;
    loadA(0); loadB(0);
    stage(0);
    __syncthreads();

    for (int k0 = 0; k0 < K; k0 += 32) {
        bool more = (k0 + 32 < K);
        if (more) { loadA(k0 + 32); loadB(k0 + 32); }
#pragma unroll
        for (int ks = 0; ks < 2; ks++) {
            unsigned a[2][4], b[NFRAG][2];
#pragma unroll
            for (int mfi = 0; mfi < 2; mfi++) {
                uint4 t = *(const uint4*)&As[p][(((wm * 2 + mfi) * 2 + ks) * 32 + lane) * 4];
                a[mfi][0] = t.x; a[mfi][1] = t.y; a[mfi][2] = t.z; a[mfi][3] = t.w;
            }
#pragma unroll
            for (int nfi = 0; nfi < NFRAG; nfi++) {
                uint2 t = *(const uint2*)&Bs[p][(((wn * NFRAG + nfi) * 2 + ks) * 32 + lane) * 2];
                b[nfi][0] = t.x; b[nfi][1] = t.y;
            }
#pragma unroll
            for (int mfi = 0; mfi < 2; mfi++)
#pragma unroll
                for (int nfi = 0; nfi < NFRAG; nfi++)
                    mma16(acc[mfi][nfi], a[mfi], b[nfi]);
        }
        if (more) { stage(1 - p); p ^= 1; __syncthreads(); }
    }

    float* Cf = (float*)Cv;
    __half* Ch = (__half*)Cv;
#pragma unroll
    for (int mfi = 0; mfi < 2; mfi++) {
#pragma unroll
        for (int nfi = 0; nfi < NFRAG; nfi++) {
            int row = m0 + wm * 32 + mfi * 16 + (lane >> 2);
            int col = n0 + wn * (BN / 2) + nfi * 8 + (lane & 3) * 2;
            float2 v0 = make_float2(acc[mfi][nfi][0] * alpha, acc[mfi][nfi][1] * alpha);
            float2 v1 = make_float2(acc[mfi][nfi][2] * alpha, acc[mfi][nfi][3] * alpha);
            if constexpr (RES) {
                float2 r0 = *(const float2*)(R + (size_t)row * ldC + col);
                float2 r1 = *(const float2*)(R + (size_t)(row + 8) * ldC + col);
                v0.x += r0.x; v0.y += r0.y; v1.x += r1.x; v1.y += r1.y;
            }
            if constexpr (OH) {
                *(__half2*)(Ch + (size_t)row * ldC + col) = __floats2half2_rn(v0.x, v0.y);
                *(__half2*)(Ch + (size_t)(row + 8) * ldC + col) = __floats2half2_rn(v1.x, v1.y);
            } else {
                *(float2*)(Cf + (size_t)row * ldC + col) = v0;
                *(float2*)(Cf + (size_t)(row + 8) * ldC + col) = v1;
            }
        }
    }
}

// ---------------------------------------------------------------------------
// GEMM wrappers
// ---------------------------------------------------------------------------
// qkv^T[b][n][o] = xn[b][n][c] @ W[o][c]^T   (M=1024 pix, N=1536, K=512)
__global__ void __launch_bounds__(256) k_qkv() {
    int b = blockIdx.z;
    gemm16<128, false, true, false>(
        g_xnh + (size_t)b * NPIX * CCH, CCH,
        g_wqkvh, CCH,
        g_qkvt + (size_t)b * NPIX * QKVC, QKVC, nullptr, CCH, 1.f);
}
// sim[bh][i][j] = SCALE * q[i][c] k[j][c]   (M=N=1024, K=64)
__global__ void __launch_bounds__(256) k_qk() {
    int bh = blockIdx.z, b = bh >> 3, h = bh & 7;
    const __half* base = g_qkvt + (size_t)b * NPIX * QKVC;
    gemm16<128, false, false, false>(
        base + h * 64, QKVC,            // A = q [i][c]
        base + 512 + h * 64, QKVC,      // B = k [j][c] (mem [N][K])
        g_sim + (size_t)bh * NPIX * NPIX, NPIX, nullptr, 64, SCALEF);
}
// att[b][i][h*64+c] = P[i][j] V[j][c]   (M=1024, N=64, K=1024)
__global__ void __launch_bounds__(256) k_pv() {
    int bh = blockIdx.z, b = bh >> 3, h = bh & 7;
    gemm16<64, true, true, false>(
        g_ph + (size_t)bh * NPIX * NPIX, NPIX,              // A = P [i][j]
        g_qkvt + (size_t)b * NPIX * QKVC + 1024 + h * 64, QKVC, // B = V mem [j][c] = [K][N]
        g_atth + (size_t)b * NPIX * CCH + h * 64, CCH, nullptr, NPIX, 1.f);
}
// out[b][o][n] = W_out[o][c] att[n][c]^T + x   (M=512, N=1024, K=512)
__global__ void __launch_bounds__(256) k_out(const float* __restrict__ X,
                                             float* __restrict__ O) {
    int b = blockIdx.z;
    gemm16<128, false, false, true>(
        g_wouth, CCH,
        g_atth + (size_t)b * NPIX * CCH, CCH,
        O + (size_t)b * CCH * NPIX, NPIX,
        X + (size_t)b * CCH * NPIX, CCH, 1.f);
}

// ---------------------------------------------------------------------------
// Weight conversion fp32 -> fp16 (one-shot, tiny)
// ---------------------------------------------------------------------------
__global__ void wconv(const float* __restrict__ wq, const float* __restrict__ wo) {
    int i = blockIdx.x * 256 + threadIdx.x;
    if (i < QKVC * CCH) g_wqkvh[i] = __float2half_rn(wq[i]);
    if (i < CCH * CCH)  g_wouth[i] = __float2half_rn(wo[i]);
}

// ---------------------------------------------------------------------------
// Channel LayerNorm; writes g_xnh transposed [b][n][c] (half) via smem tile.
// ---------------------------------------------------------------------------
__global__ void ln_kernel(const float* __restrict__ x, const float* __restrict__ gamma) {
    int b = blockIdx.y, n0 = blockIdx.x * 32;
    int tx = threadIdx.x, ty = threadIdx.y;
    const float* xb = x + (size_t)b * CCH * NPIX + n0 + tx;

    float s = 0.f, s2 = 0.f;
    for (int c = ty; c < CCH; c += 8) {
        float v = xb[(size_t)c * NPIX];
        s += v; s2 += v * v;
    }
    __shared__ float sh1[8][32], sh2[8][32];
    sh1[ty][tx] = s; sh2[ty][tx] = s2;
    __syncthreads();
    float S = 0.f, S2 = 0.f;
#pragma unroll
    for (int r = 0; r < 8; r++) { S += sh1[r][tx]; S2 += sh2[r][tx]; }
    float mean = S * (1.f / CCH);
    float var  = S2 * (1.f / CCH) - mean * mean;
    float rstd = rsqrtf(var + EPSLN);

    __shared__ float tile[32][72];
    __half* xo = g_xnh + (size_t)b * NPIX * CCH;
    int tid = ty * 32 + tx;
    for (int c0 = 0; c0 < CCH; c0 += 64) {
#pragma unroll
        for (int j = 0; j < 8; j++) {
            int c = c0 + ty * 8 + j;
            tile[tx][ty * 8 + j] = (xb[(size_t)c * NPIX] - mean) * rstd * gamma[c];
        }
        __syncthreads();
        int row = tid >> 3, cq = (tid & 7) * 8;
        float4 a = *(float4*)&tile[row][cq];
        float4 bq = *(float4*)&tile[row][cq + 4];
        __half2 h[4] = {__floats2half2_rn(a.x, a.y),  __floats2half2_rn(a.z, a.w),
                        __floats2half2_rn(bq.x, bq.y), __floats2half2_rn(bq.z, bq.w)};
        *(uint4*)(xo + (size_t)(n0 + row) * CCH + c0 + cq) = *(uint4*)h;
        __syncthreads();
    }
}

// ---------------------------------------------------------------------------
// Row softmax: f32 logits in, half probs out.
// ---------------------------------------------------------------------------
__global__ void softmax_k() {
    size_t row = blockIdx.x;
    const float* p = g_sim + row * NPIX;
    __half* po = g_ph + row * NPIX;
    int t = threadIdx.x;

    float v[8];
    float mx = -1e30f;
#pragma unroll
    for (int r = 0; r < 8; r++) { v[r] = p[t + 128 * r]; mx = fmaxf(mx, v[r]); }
#pragma unroll
    for (int o = 16; o; o >>= 1) mx = fmaxf(mx, __shfl_xor_sync(0xffffffffu, mx, o));
    __shared__ float sm[4], ss[4];
    if ((t & 31) == 0) sm[t >> 5] = mx;
    __syncthreads();
    mx = fmaxf(fmaxf(sm[0], sm[1]), fmaxf(sm[2], sm[3]));

    float s = 0.f;
#pragma unroll
    for (int r = 0; r < 8; r++) { v[r] = __expf(v[r] - mx); s += v[r]; }
#pragma unroll
    for (int o = 16; o; o >>= 1) s += __shfl_xor_sync(0xffffffffu, s, o);
    if ((t & 31) == 0) ss[t >> 5] = s;
    __syncthreads();
    s = ss[0] + ss[1] + ss[2] + ss[3];
    float inv = 1.0f / s;
#pragma unroll
    for (int r = 0; r < 8; r++) po[t + 128 * r] = __float2half_rn(v[r] * inv);
}

// ---------------------------------------------------------------------------
extern "C" void kernel_launch(void* const* d_in, const int* in_sizes, int n_in,
                              void* d_out, int out_size) {
    const float* x     = (const float*)d_in[0];
    const float* gamma = (const float*)d_in[1];
    const float* w_qkv = (const float*)d_in[2];
    const float* w_out = (const float*)d_in[3];
    float* out = (float*)d_out;

    wconv<<<(QKVC * CCH + 255) / 256, 256>>>(w_qkv, w_out);
    ln_kernel<<<dim3(NPIX / 32, BATCH), dim3(32, 8)>>>(x, gamma);
    k_qkv<<<dim3(QKVC / 128, NPIX / 128, BATCH), 256>>>();
    k_qk <<<dim3(NPIX / 128, NPIX / 128, BHTOT), 256>>>();
    softmax_k<<<dim3(BHTOT * NPIX), 128>>>();
    k_pv <<<dim3(1, NPIX / 128, BHTOT), 256>>>();
    k_out<<<dim3(NPIX / 128, CCH / 128, BATCH), 256>>>(x, out);
}